// round 1
// baseline (speedup 1.0000x reference)
#include <cuda_runtime.h>
#include <math.h>

// ---------------- problem constants ----------------
#define D     1024
#define FF    4096
#define BB    4
#define SS    512          // S == T == 512
#define HH    16
#define DKH   64           // D / H
#define LL    4
#define MROWS (BB*SS)      // 2048
#define BHN   (BB*HH)      // 64

#define FLAG_RELU 1
#define FLAG_RES  2

// ---------------- scratch (device globals; no allocation allowed) ----------
__device__ float g_x [MROWS*D];
__device__ float g_y [MROWS*D];
__device__ float g_q [MROWS*D];
__device__ float g_k [MROWS*D];
__device__ float g_v [MROWS*D];
__device__ float g_ao[MROWS*D];
__device__ float g_t0[MROWS*D];
__device__ float g_h [MROWS*FF];
__device__ float g_sc[(size_t)BHN*SS*SS];

// ---------------- SGEMM: C = A[M,K] @ W[K,N] + bias (+relu / +res) --------
#define BM 128
#define BN 128
#define BK 16

__global__ __launch_bounds__(256) void sgemm_kernel(
    const float* __restrict__ A, const float* __restrict__ W,
    const float* __restrict__ bias, const float* __restrict__ res,
    float* __restrict__ C, int M, int N, int K, int flags)
{
    __shared__ float As[BK][BM];
    __shared__ float Bs[BK][BN];
    const int tid = threadIdx.x;
    const int bm  = blockIdx.y * BM;
    const int bn  = blockIdx.x * BN;
    const int tx  = tid & 15;       // 16 cols of 8
    const int ty  = tid >> 4;       // 16 rows of 8

    float acc[8][8];
#pragma unroll
    for (int i = 0; i < 8; i++)
#pragma unroll
        for (int j = 0; j < 8; j++) acc[i][j] = 0.0f;

    for (int k0 = 0; k0 < K; k0 += BK) {
#pragma unroll
        for (int i = 0; i < 2; i++) {
            int idx = tid + i * 256;                 // 0..511
            // A tile: 128 rows x 16 cols  (512 float4)
            int r  = idx >> 2;
            int c  = (idx & 3) << 2;
            float4 va = *(const float4*)(A + (size_t)(bm + r) * K + k0 + c);
            As[c + 0][r] = va.x; As[c + 1][r] = va.y;
            As[c + 2][r] = va.z; As[c + 3][r] = va.w;
            // W tile: 16 rows x 128 cols (512 float4)
            int rb = idx >> 5;
            int cb = (idx & 31) << 2;
            *(float4*)&Bs[rb][cb] =
                *(const float4*)(W + (size_t)(k0 + rb) * N + bn + cb);
        }
        __syncthreads();
#pragma unroll
        for (int kk = 0; kk < BK; kk++) {
            float4 a0 = *(float4*)&As[kk][ty * 8];
            float4 a1 = *(float4*)&As[kk][ty * 8 + 4];
            float4 b0 = *(float4*)&Bs[kk][tx * 8];
            float4 b1 = *(float4*)&Bs[kk][tx * 8 + 4];
            float ar[8] = {a0.x, a0.y, a0.z, a0.w, a1.x, a1.y, a1.z, a1.w};
            float br[8] = {b0.x, b0.y, b0.z, b0.w, b1.x, b1.y, b1.z, b1.w};
#pragma unroll
            for (int i = 0; i < 8; i++)
#pragma unroll
                for (int j = 0; j < 8; j++)
                    acc[i][j] = fmaf(ar[i], br[j], acc[i][j]);
        }
        __syncthreads();
    }

#pragma unroll
    for (int i = 0; i < 8; i++) {
        int row = bm + ty * 8 + i;
#pragma unroll
        for (int j4 = 0; j4 < 8; j4 += 4) {
            int col = bn + tx * 8 + j4;
            float4 v;
            v.x = acc[i][j4 + 0]; v.y = acc[i][j4 + 1];
            v.z = acc[i][j4 + 2]; v.w = acc[i][j4 + 3];
            if (bias) {
                v.x += bias[col + 0]; v.y += bias[col + 1];
                v.z += bias[col + 2]; v.w += bias[col + 3];
            }
            if (flags & FLAG_RELU) {
                v.x = fmaxf(v.x, 0.f); v.y = fmaxf(v.y, 0.f);
                v.z = fmaxf(v.z, 0.f); v.w = fmaxf(v.w, 0.f);
            }
            if (flags & FLAG_RES) {
                float4 r4 = *(const float4*)(res + (size_t)row * N + col);
                v.x += r4.x; v.y += r4.y; v.z += r4.z; v.w += r4.w;
            }
            *(float4*)(C + (size_t)row * N + col) = v;
        }
    }
}

// ---------------- embedding + positional encoding -------------------------
__global__ void embed_kernel(const int* __restrict__ toks,
                             const float* __restrict__ emb,
                             float* __restrict__ out, int Sdim)
{
    int rs  = blockIdx.x;                 // b*Sdim + pos
    int pos = rs % Sdim;
    int tok = toks[rs];
    int j   = threadIdx.x * 4;
    float4 e = *(const float4*)(emb + (size_t)tok * D + j);
    float ev[4] = {e.x, e.y, e.z, e.w};
    float ov[4];
    const float c = 9.210340371976184f / (float)D;   // ln(10000)/D
#pragma unroll
    for (int q = 0; q < 4; q++) {
        int jj  = j + q;
        float div = expf(-(float)(jj & ~1) * c);
        float ang = (float)pos * div;
        float pe  = (jj & 1) ? cosf(ang) : sinf(ang);
        ov[q] = ev[q] + pe;
    }
    float4 o = {ov[0], ov[1], ov[2], ov[3]};
    *(float4*)(out + (size_t)rs * D + j) = o;
}

// ---------------- scores = QK^T * scale, mask fused ------------------------
// grid: (SS/64, SS/64, B*H), block 256
__global__ __launch_bounds__(256) void attn_scores_kernel(
    const float* __restrict__ Q, const float* __restrict__ Km,
    const int* __restrict__ toks, float* __restrict__ sc, int causal)
{
    int kt = blockIdx.x * 64;
    int qt = blockIdx.y * 64;
    int bh = blockIdx.z;
    int b  = bh / HH, h = bh % HH;
    __shared__ float Qs[DKH][64];   // [d][q]
    __shared__ float Ks[DKH][64];   // [d][k]
    int tid = threadIdx.x;
#pragma unroll
    for (int i = 0; i < 4; i++) {
        int idx = tid + i * 256;            // 0..1023
        int r   = idx >> 4;                 // 0..63
        int c   = (idx & 15) << 2;          // 0..60
        float4 vq = *(const float4*)(Q + (size_t)(b * SS + qt + r) * D + h * DKH + c);
        Qs[c + 0][r] = vq.x; Qs[c + 1][r] = vq.y;
        Qs[c + 2][r] = vq.z; Qs[c + 3][r] = vq.w;
        float4 vk = *(const float4*)(Km + (size_t)(b * SS + kt + r) * D + h * DKH + c);
        Ks[c + 0][r] = vk.x; Ks[c + 1][r] = vk.y;
        Ks[c + 2][r] = vk.z; Ks[c + 3][r] = vk.w;
    }
    __syncthreads();
    int tx = tid & 15, ty = tid >> 4;       // k-cols tx*4.., q-rows ty*4..
    float acc[4][4];
#pragma unroll
    for (int i = 0; i < 4; i++)
#pragma unroll
        for (int j = 0; j < 4; j++) acc[i][j] = 0.0f;

#pragma unroll
    for (int d = 0; d < DKH; d++) {
        float4 q4 = *(float4*)&Qs[d][ty * 4];
        float4 k4 = *(float4*)&Ks[d][tx * 4];
        float qv[4] = {q4.x, q4.y, q4.z, q4.w};
        float kv[4] = {k4.x, k4.y, k4.z, k4.w};
#pragma unroll
        for (int i = 0; i < 4; i++)
#pragma unroll
            for (int j = 0; j < 4; j++)
                acc[i][j] = fmaf(qv[i], kv[j], acc[i][j]);
    }
    const float scale = 0.125f;             // 1/sqrt(64)
#pragma unroll
    for (int i = 0; i < 4; i++) {
        int q = qt + ty * 4 + i;
#pragma unroll
        for (int j = 0; j < 4; j++) {
            int k = kt + tx * 4 + j;
            bool valid = toks[b * SS + k] != 0;
            if (causal) valid = valid && (k <= q);
            sc[((size_t)bh * SS + q) * SS + k] = valid ? acc[i][j] * scale : -1e9f;
        }
    }
}

// ---------------- row softmax (one warp per 512-wide row) ------------------
__global__ void softmax_kernel(float* __restrict__ sc)
{
    int gw   = (blockIdx.x * blockDim.x + threadIdx.x) >> 5;   // row id
    int lane = threadIdx.x & 31;
    float* row = sc + (size_t)gw * SS;
    float4 v[4];
    float mx = -1e30f;
#pragma unroll
    for (int i = 0; i < 4; i++) {
        v[i] = *(float4*)(row + lane * 4 + i * 128);
        mx = fmaxf(mx, fmaxf(fmaxf(v[i].x, v[i].y), fmaxf(v[i].z, v[i].w)));
    }
#pragma unroll
    for (int o = 16; o > 0; o >>= 1)
        mx = fmaxf(mx, __shfl_xor_sync(0xffffffffu, mx, o));
    float sum = 0.0f;
#pragma unroll
    for (int i = 0; i < 4; i++) {
        v[i].x = expf(v[i].x - mx); v[i].y = expf(v[i].y - mx);
        v[i].z = expf(v[i].z - mx); v[i].w = expf(v[i].w - mx);
        sum += v[i].x + v[i].y + v[i].z + v[i].w;
    }
#pragma unroll
    for (int o = 16; o > 0; o >>= 1)
        sum += __shfl_xor_sync(0xffffffffu, sum, o);
    float inv = 1.0f / sum;
#pragma unroll
    for (int i = 0; i < 4; i++) {
        v[i].x *= inv; v[i].y *= inv; v[i].z *= inv; v[i].w *= inv;
        *(float4*)(row + lane * 4 + i * 128) = v[i];
    }
}

// ---------------- O = P @ V  (per batch-head) ------------------------------
// grid: (SS/64, B*H), block 256
__global__ __launch_bounds__(256) void attn_av_kernel(
    const float* __restrict__ sc, const float* __restrict__ V,
    float* __restrict__ O)
{
    int qt = blockIdx.x * 64;
    int bh = blockIdx.y;
    int b  = bh / HH, h = bh % HH;
    __shared__ float Ps[64][68];    // [q][k] (padded)
    __shared__ float Vs[64][64];    // [k][d]
    int tid = threadIdx.x;
    int tx = tid & 15, ty = tid >> 4;
    float acc[4][4];
#pragma unroll
    for (int i = 0; i < 4; i++)
#pragma unroll
        for (int j = 0; j < 4; j++) acc[i][j] = 0.0f;

    for (int k0 = 0; k0 < SS; k0 += 64) {
#pragma unroll
        for (int i = 0; i < 4; i++) {
            int idx = tid + i * 256;
            int r   = idx >> 4;
            int c   = (idx & 15) << 2;
            *(float4*)&Ps[r][c] =
                *(const float4*)(sc + ((size_t)bh * SS + qt + r) * SS + k0 + c);
            *(float4*)&Vs[r][c] =
                *(const float4*)(V + (size_t)(b * SS + k0 + r) * D + h * DKH + c);
        }
        __syncthreads();
#pragma unroll
        for (int kk = 0; kk < 64; kk++) {
            float4 v4 = *(float4*)&Vs[kk][tx * 4];
            float vv[4] = {v4.x, v4.y, v4.z, v4.w};
#pragma unroll
            for (int i = 0; i < 4; i++) {
                float p = Ps[ty * 4 + i][kk];
#pragma unroll
                for (int j = 0; j < 4; j++)
                    acc[i][j] = fmaf(p, vv[j], acc[i][j]);
            }
        }
        __syncthreads();
    }
#pragma unroll
    for (int i = 0; i < 4; i++) {
        int q = qt + ty * 4 + i;
        float4 o = {acc[i][0], acc[i][1], acc[i][2], acc[i][3]};
        *(float4*)(O + (size_t)(b * SS + q) * D + h * DKH + tx * 4) = o;
    }
}

// ---------------- out = LayerNorm(x + a) * s + b ---------------------------
// grid = MROWS, block 256 (4 elems/thread)
__global__ void add_ln_kernel(const float* __restrict__ x,
                              const float* __restrict__ a,
                              const float* __restrict__ s,
                              const float* __restrict__ bb,
                              float* __restrict__ out)
{
    __shared__ float red[8];
    __shared__ float bc;
    int row = blockIdx.x, tid = threadIdx.x;
    int lane = tid & 31, wid = tid >> 5;
    const float* xr = x + (size_t)row * D;
    const float* ar = a + (size_t)row * D;
    float4 xv = *(const float4*)(xr + tid * 4);
    float4 av = *(const float4*)(ar + tid * 4);
    float v[4] = {xv.x + av.x, xv.y + av.y, xv.z + av.z, xv.w + av.w};

    float sum = v[0] + v[1] + v[2] + v[3];
#pragma unroll
    for (int o = 16; o > 0; o >>= 1) sum += __shfl_xor_sync(0xffffffffu, sum, o);
    if (lane == 0) red[wid] = sum;
    __syncthreads();
    if (tid == 0) {
        float t = 0.f;
#pragma unroll
        for (int i = 0; i < 8; i++) t += red[i];
        bc = t * (1.0f / D);
    }
    __syncthreads();
    float mean = bc;

    float d0 = v[0] - mean, d1 = v[1] - mean, d2 = v[2] - mean, d3 = v[3] - mean;
    float sq = d0 * d0 + d1 * d1 + d2 * d2 + d3 * d3;
#pragma unroll
    for (int o = 16; o > 0; o >>= 1) sq += __shfl_xor_sync(0xffffffffu, sq, o);
    __syncthreads();
    if (lane == 0) red[wid] = sq;
    __syncthreads();
    if (tid == 0) {
        float t = 0.f;
#pragma unroll
        for (int i = 0; i < 8; i++) t += red[i];
        bc = rsqrtf(t * (1.0f / D) + 1e-5f);
    }
    __syncthreads();
    float rstd = bc;

    float4 sv = *(const float4*)(s + tid * 4);
    float4 bv = *(const float4*)(bb + tid * 4);
    float4 o;
    o.x = d0 * rstd * sv.x + bv.x;
    o.y = d1 * rstd * sv.y + bv.y;
    o.z = d2 * rstd * sv.z + bv.z;
    o.w = d3 * rstd * sv.w + bv.w;
    *(float4*)(out + (size_t)row * D + tid * 4) = o;
}

// ---------------- host orchestration ---------------------------------------
static void run_mha(const float* xq, const float* xkv,
                    const float* w, const float* bias,
                    const int* toks, int causal,
                    float* pq, float* pk, float* pv, float* pao, float* psc,
                    float* out)
{
    dim3 gP(D / BN, MROWS / BM);   // (8,16)
    sgemm_kernel<<<gP, 256>>>(xq,  w + 0 * D * D, bias + 0 * D, nullptr, pq, MROWS, D, D, 0);
    sgemm_kernel<<<gP, 256>>>(xkv, w + 1 * D * D, bias + 1 * D, nullptr, pk, MROWS, D, D, 0);
    sgemm_kernel<<<gP, 256>>>(xkv, w + 2 * D * D, bias + 2 * D, nullptr, pv, MROWS, D, D, 0);
    attn_scores_kernel<<<dim3(SS / 64, SS / 64, BHN), 256>>>(pq, pk, toks, psc, causal);
    softmax_kernel<<<(BHN * SS) / 8, 256>>>(psc);
    attn_av_kernel<<<dim3(SS / 64, BHN), 256>>>(psc, pv, pao);
    sgemm_kernel<<<gP, 256>>>(pao, w + 3 * D * D, bias + 3 * D, nullptr, out, MROWS, D, D, 0);
}

extern "C" void kernel_launch(void* const* d_in, const int* in_sizes, int n_in,
                              void* d_out, int out_size)
{
    (void)in_sizes; (void)n_in; (void)out_size;
    const int*   src       = (const int*)  d_in[0];
    const int*   tgt       = (const int*)  d_in[1];
    const float* src_emb   = (const float*)d_in[2];
    const float* tgt_emb   = (const float*)d_in[3];
    const float* eaw       = (const float*)d_in[4];
    const float* eab       = (const float*)d_in[5];
    const float* ew1       = (const float*)d_in[6];
    const float* eb1       = (const float*)d_in[7];
    const float* ew2       = (const float*)d_in[8];
    const float* eb2       = (const float*)d_in[9];
    const float* els       = (const float*)d_in[10];
    const float* elb       = (const float*)d_in[11];
    const float* daw       = (const float*)d_in[12];
    const float* dab       = (const float*)d_in[13];
    const float* dw1       = (const float*)d_in[14];
    const float* db1       = (const float*)d_in[15];
    const float* dw2       = (const float*)d_in[16];
    const float* db2       = (const float*)d_in[17];
    const float* dls       = (const float*)d_in[18];
    const float* dlb       = (const float*)d_in[19];
    float* out = (float*)d_out;

    float *px, *py, *pq, *pk, *pv, *pao, *pt0, *ph, *psc;
    cudaGetSymbolAddress((void**)&px,  g_x);
    cudaGetSymbolAddress((void**)&py,  g_y);
    cudaGetSymbolAddress((void**)&pq,  g_q);
    cudaGetSymbolAddress((void**)&pk,  g_k);
    cudaGetSymbolAddress((void**)&pv,  g_v);
    cudaGetSymbolAddress((void**)&pao, g_ao);
    cudaGetSymbolAddress((void**)&pt0, g_t0);
    cudaGetSymbolAddress((void**)&ph,  g_h);
    cudaGetSymbolAddress((void**)&psc, g_sc);

    dim3 gP(D / BN, MROWS / BM);    // N=1024 GEMMs
    dim3 gF(FF / BN, MROWS / BM);   // N=4096 GEMMs

    // ----- encoder -----
    embed_kernel<<<MROWS, 256>>>(src, src_emb, px, SS);
    for (int i = 0; i < LL; i++) {
        run_mha(px, px, eaw + (size_t)i * 4 * D * D, eab + (size_t)i * 4 * D,
                src, 0, pq, pk, pv, pao, psc, pt0);
        add_ln_kernel<<<MROWS, 256>>>(px, pt0, els + (size_t)(i * 2 + 0) * D,
                                      elb + (size_t)(i * 2 + 0) * D, px);
        sgemm_kernel<<<gF, 256>>>(px, ew1 + (size_t)i * D * FF, eb1 + (size_t)i * FF,
                                  nullptr, ph, MROWS, FF, D, FLAG_RELU);
        // f = h @ w2 + b2 + x   (double residual, as in reference)
        sgemm_kernel<<<gP, 256>>>(ph, ew2 + (size_t)i * FF * D, eb2 + (size_t)i * D,
                                  px, pt0, MROWS, D, FF, FLAG_RES);
        add_ln_kernel<<<MROWS, 256>>>(px, pt0, els + (size_t)(i * 2 + 1) * D,
                                      elb + (size_t)(i * 2 + 1) * D, px);
    }

    // ----- decoder -----
    embed_kernel<<<MROWS, 256>>>(tgt, tgt_emb, py, SS);
    for (int i = 0; i < LL; i++) {
        // self-attention (causal + tgt pad mask)
        run_mha(py, py, daw + (size_t)(i * 2 + 0) * 4 * D * D,
                dab + (size_t)(i * 2 + 0) * 4 * D,
                tgt, 1, pq, pk, pv, pao, psc, pt0);
        add_ln_kernel<<<MROWS, 256>>>(py, pt0, dls + (size_t)(i * 3 + 0) * D,
                                      dlb + (size_t)(i * 3 + 0) * D, py);
        // cross-attention (keys/values from encoder output, src pad mask)
        run_mha(py, px, daw + (size_t)(i * 2 + 1) * 4 * D * D,
                dab + (size_t)(i * 2 + 1) * 4 * D,
                src, 0, pq, pk, pv, pao, psc, pt0);
        add_ln_kernel<<<MROWS, 256>>>(py, pt0, dls + (size_t)(i * 3 + 1) * D,
                                      dlb + (size_t)(i * 3 + 1) * D, py);
        // FFN (single residual via add_ln)
        sgemm_kernel<<<gF, 256>>>(py, dw1 + (size_t)i * D * FF, db1 + (size_t)i * FF,
                                  nullptr, ph, MROWS, FF, D, FLAG_RELU);
        sgemm_kernel<<<gP, 256>>>(ph, dw2 + (size_t)i * FF * D, db2 + (size_t)i * D,
                                  nullptr, pt0, MROWS, D, FF, 0);
        float* dst = (i == LL - 1) ? out : py;
        add_ln_kernel<<<MROWS, 256>>>(py, pt0, dls + (size_t)(i * 3 + 2) * D,
                                      dlb + (size_t)(i * 3 + 2) * D, dst);
    }
}

// round 3
// speedup vs baseline: 2.3763x; 2.3763x over previous
#include <cuda_runtime.h>
#include <math.h>
#include <stdint.h>

// ---------------- problem constants ----------------
#define D     1024
#define FF    4096
#define BB    4
#define SS    512          // S == T == 512
#define HH    16
#define DKH   64           // D / H
#define LL    4
#define MROWS (BB*SS)      // 2048
#define BHN   (BB*HH)      // 64

#define FLAG_RELU 1
#define FLAG_RES  2

// ---------------- scratch (device globals; no allocation allowed) ----------
__device__ float g_x [MROWS*D];
__device__ float g_y [MROWS*D];
__device__ float g_q [MROWS*D];
__device__ float g_k [MROWS*D];
__device__ float g_v [MROWS*D];
__device__ float g_ao[MROWS*D];
__device__ float g_t0[MROWS*D];
__device__ float g_h [MROWS*FF];
__device__ float g_sc[(size_t)BHN*SS*SS];

// ---------------- TF32 tensor-core GEMM -------------------------------------
// C = A[M,K] @ W[K,N] + bias (+relu / +res)
// 128x128 block tile, BK=16, 8 warps, warp tile 64x32 (4x4 m16n8k8 mma tiles).
// fp32 -> tf32 via cvt.rna at smem-store time (unbiased rounding).
#define BKT 16

__device__ __forceinline__ uint32_t f2tf32(float f) {
    uint32_t u;
    asm("cvt.rna.tf32.f32 %0, %1;" : "=r"(u) : "f"(f));
    return u;
}

__device__ __forceinline__ void mma_tf32(float c[4], const uint32_t a[4],
                                         const uint32_t b[2]) {
    asm volatile(
        "mma.sync.aligned.m16n8k8.row.col.f32.tf32.tf32.f32 "
        "{%0,%1,%2,%3}, {%4,%5,%6,%7}, {%8,%9}, {%0,%1,%2,%3};"
        : "+f"(c[0]), "+f"(c[1]), "+f"(c[2]), "+f"(c[3])
        : "r"(a[0]), "r"(a[1]), "r"(a[2]), "r"(a[3]), "r"(b[0]), "r"(b[1]));
}

__global__ __launch_bounds__(256) void sgemm_tf32(
    const float* __restrict__ A, const float* __restrict__ W,
    const float* __restrict__ bias, const float* __restrict__ res,
    float* __restrict__ C, int M, int N, int K, int flags)
{
    __shared__ uint32_t As[2][128][BKT + 4];   // [m][k], stride 20 (conflict-free)
    __shared__ uint32_t Bs[2][BKT][136];       // [k][n], stride 136 == 8 mod 32

    const int tid  = threadIdx.x;
    const int lane = tid & 31, wrp = tid >> 5;
    const int wm   = (wrp >> 2) * 64;          // warp row base (0 or 64)
    const int wn   = (wrp & 3) * 32;           // warp col base (0..96)
    const int l4   = lane >> 2, lq = lane & 3;
    const int bm   = blockIdx.y * 128, bn = blockIdx.x * 128;

    // A tile: 128 rows x 16 cols. Each thread: row tid/2, 8 floats at (tid&1)*8.
    const int ar = tid >> 1;
    const int ac = (tid & 1) * 8;
    // B tile: 16 rows x 128 cols. Each thread: row tid/16, 8 floats at (tid&15)*8.
    const int br = tid >> 4;
    const int bc = (tid & 15) * 8;

    const float* Aptr = A + (size_t)(bm + ar) * K + ac;
    const float* Wptr = W + (size_t)br * N + bn + bc;

    float acc[4][4][4];
#pragma unroll
    for (int i = 0; i < 4; i++)
#pragma unroll
        for (int j = 0; j < 4; j++)
#pragma unroll
            for (int r = 0; r < 4; r++) acc[i][j][r] = 0.0f;

    const int nt = K / BKT;

    // prologue: tile 0 -> smem buf 0
    {
        float4 a0 = *(const float4*)(Aptr + 0);
        float4 a1 = *(const float4*)(Aptr + 4);
        float4 b0 = *(const float4*)(Wptr + 0);
        float4 b1 = *(const float4*)(Wptr + 4);
        uint32_t* as = &As[0][ar][ac];
        as[0] = f2tf32(a0.x); as[1] = f2tf32(a0.y);
        as[2] = f2tf32(a0.z); as[3] = f2tf32(a0.w);
        as[4] = f2tf32(a1.x); as[5] = f2tf32(a1.y);
        as[6] = f2tf32(a1.z); as[7] = f2tf32(a1.w);
        uint32_t* bs = &Bs[0][br][bc];
        bs[0] = f2tf32(b0.x); bs[1] = f2tf32(b0.y);
        bs[2] = f2tf32(b0.z); bs[3] = f2tf32(b0.w);
        bs[4] = f2tf32(b1.x); bs[5] = f2tf32(b1.y);
        bs[6] = f2tf32(b1.z); bs[7] = f2tf32(b1.w);
    }
    __syncthreads();

    for (int t = 0; t < nt; t++) {
        const int buf = t & 1;
        float4 pa0, pa1, pb0, pb1;
        if (t + 1 < nt) {
            const float* Ap = Aptr + (size_t)(t + 1) * BKT;
            const float* Wp = Wptr + (size_t)(t + 1) * BKT * N;
            pa0 = *(const float4*)(Ap + 0);
            pa1 = *(const float4*)(Ap + 4);
            pb0 = *(const float4*)(Wp + 0);
            pb1 = *(const float4*)(Wp + 4);
        }

        // compute current buffer: 2 k-steps of 8
#pragma unroll
        for (int ks = 0; ks < BKT; ks += 8) {
            uint32_t af[4][4], bf[4][2];
#pragma unroll
            for (int tm = 0; tm < 4; tm++) {
                const int m0 = wm + tm * 16 + l4;
                af[tm][0] = As[buf][m0][ks + lq];
                af[tm][1] = As[buf][m0 + 8][ks + lq];
                af[tm][2] = As[buf][m0][ks + lq + 4];
                af[tm][3] = As[buf][m0 + 8][ks + lq + 4];
            }
#pragma unroll
            for (int tn = 0; tn < 4; tn++) {
                const int n0 = wn + tn * 8 + l4;
                bf[tn][0] = Bs[buf][ks + lq][n0];
                bf[tn][1] = Bs[buf][ks + lq + 4][n0];
            }
#pragma unroll
            for (int tm = 0; tm < 4; tm++)
#pragma unroll
                for (int tn = 0; tn < 4; tn++)
                    mma_tf32(acc[tm][tn], af[tm], bf[tn]);
        }

        if (t + 1 < nt) {
            const int nb = buf ^ 1;
            uint32_t* as = &As[nb][ar][ac];
            as[0] = f2tf32(pa0.x); as[1] = f2tf32(pa0.y);
            as[2] = f2tf32(pa0.z); as[3] = f2tf32(pa0.w);
            as[4] = f2tf32(pa1.x); as[5] = f2tf32(pa1.y);
            as[6] = f2tf32(pa1.z); as[7] = f2tf32(pa1.w);
            uint32_t* bs = &Bs[nb][br][bc];
            bs[0] = f2tf32(pb0.x); bs[1] = f2tf32(pb0.y);
            bs[2] = f2tf32(pb0.z); bs[3] = f2tf32(pb0.w);
            bs[4] = f2tf32(pb1.x); bs[5] = f2tf32(pb1.y);
            bs[6] = f2tf32(pb1.z); bs[7] = f2tf32(pb1.w);
        }
        __syncthreads();
    }

    // epilogue
#pragma unroll
    for (int tm = 0; tm < 4; tm++) {
        const int r0 = bm + wm + tm * 16 + l4;
        const int r1 = r0 + 8;
#pragma unroll
        for (int tn = 0; tn < 4; tn++) {
            const int col = bn + wn + tn * 8 + lq * 2;
            float2 v0 = {acc[tm][tn][0], acc[tm][tn][1]};
            float2 v1 = {acc[tm][tn][2], acc[tm][tn][3]};
            if (bias) {
                float2 bv = *(const float2*)(bias + col);
                v0.x += bv.x; v0.y += bv.y;
                v1.x += bv.x; v1.y += bv.y;
            }
            if (flags & FLAG_RELU) {
                v0.x = fmaxf(v0.x, 0.f); v0.y = fmaxf(v0.y, 0.f);
                v1.x = fmaxf(v1.x, 0.f); v1.y = fmaxf(v1.y, 0.f);
            }
            if (flags & FLAG_RES) {
                float2 q0 = *(const float2*)(res + (size_t)r0 * N + col);
                float2 q1 = *(const float2*)(res + (size_t)r1 * N + col);
                v0.x += q0.x; v0.y += q0.y;
                v1.x += q1.x; v1.y += q1.y;
            }
            *(float2*)(C + (size_t)r0 * N + col) = v0;
            *(float2*)(C + (size_t)r1 * N + col) = v1;
        }
    }
}

// ---------------- embedding + positional encoding -------------------------
__global__ void embed_kernel(const int* __restrict__ toks,
                             const float* __restrict__ emb,
                             float* __restrict__ out, int Sdim)
{
    int rs  = blockIdx.x;                 // b*Sdim + pos
    int pos = rs % Sdim;
    int tok = toks[rs];
    int j   = threadIdx.x * 4;
    float4 e = *(const float4*)(emb + (size_t)tok * D + j);
    float ev[4] = {e.x, e.y, e.z, e.w};
    float ov[4];
    const float c = 9.210340371976184f / (float)D;   // ln(10000)/D
#pragma unroll
    for (int q = 0; q < 4; q++) {
        int jj  = j + q;
        float div = expf(-(float)(jj & ~1) * c);
        float ang = (float)pos * div;
        float pe  = (jj & 1) ? cosf(ang) : sinf(ang);
        ov[q] = ev[q] + pe;
    }
    float4 o = {ov[0], ov[1], ov[2], ov[3]};
    *(float4*)(out + (size_t)rs * D + j) = o;
}

// ---------------- scores = QK^T * scale, mask fused ------------------------
// grid: (SS/64, SS/64, B*H), block 256
__global__ __launch_bounds__(256) void attn_scores_kernel(
    const float* __restrict__ Q, const float* __restrict__ Km,
    const int* __restrict__ toks, float* __restrict__ sc, int causal)
{
    int kt = blockIdx.x * 64;
    int qt = blockIdx.y * 64;
    int bh = blockIdx.z;
    int b  = bh / HH, h = bh % HH;
    __shared__ float Qs[DKH][64];   // [d][q]
    __shared__ float Ks[DKH][64];   // [d][k]
    int tid = threadIdx.x;
#pragma unroll
    for (int i = 0; i < 4; i++) {
        int idx = tid + i * 256;            // 0..1023
        int r   = idx >> 4;                 // 0..63
        int c   = (idx & 15) << 2;          // 0..60
        float4 vq = *(const float4*)(Q + (size_t)(b * SS + qt + r) * D + h * DKH + c);
        Qs[c + 0][r] = vq.x; Qs[c + 1][r] = vq.y;
        Qs[c + 2][r] = vq.z; Qs[c + 3][r] = vq.w;
        float4 vk = *(const float4*)(Km + (size_t)(b * SS + kt + r) * D + h * DKH + c);
        Ks[c + 0][r] = vk.x; Ks[c + 1][r] = vk.y;
        Ks[c + 2][r] = vk.z; Ks[c + 3][r] = vk.w;
    }
    __syncthreads();
    int tx = tid & 15, ty = tid >> 4;       // k-cols tx*4.., q-rows ty*4..
    float acc[4][4];
#pragma unroll
    for (int i = 0; i < 4; i++)
#pragma unroll
        for (int j = 0; j < 4; j++) acc[i][j] = 0.0f;

#pragma unroll
    for (int d = 0; d < DKH; d++) {
        float4 q4 = *(float4*)&Qs[d][ty * 4];
        float4 k4 = *(float4*)&Ks[d][tx * 4];
        float qv[4] = {q4.x, q4.y, q4.z, q4.w};
        float kv[4] = {k4.x, k4.y, k4.z, k4.w};
#pragma unroll
        for (int i = 0; i < 4; i++)
#pragma unroll
            for (int j = 0; j < 4; j++)
                acc[i][j] = fmaf(qv[i], kv[j], acc[i][j]);
    }
    const float scale = 0.125f;             // 1/sqrt(64)
#pragma unroll
    for (int i = 0; i < 4; i++) {
        int q = qt + ty * 4 + i;
#pragma unroll
        for (int j = 0; j < 4; j++) {
            int k = kt + tx * 4 + j;
            bool valid = toks[b * SS + k] != 0;
            if (causal) valid = valid && (k <= q);
            sc[((size_t)bh * SS + q) * SS + k] = valid ? acc[i][j] * scale : -1e9f;
        }
    }
}

// ---------------- row softmax (one warp per 512-wide row) ------------------
__global__ void softmax_kernel(float* __restrict__ sc)
{
    int gw   = (blockIdx.x * blockDim.x + threadIdx.x) >> 5;   // row id
    int lane = threadIdx.x & 31;
    float* row = sc + (size_t)gw * SS;
    float4 v[4];
    float mx = -1e30f;
#pragma unroll
    for (int i = 0; i < 4; i++) {
        v[i] = *(float4*)(row + lane * 4 + i * 128);
        mx = fmaxf(mx, fmaxf(fmaxf(v[i].x, v[i].y), fmaxf(v[i].z, v[i].w)));
    }
#pragma unroll
    for (int o = 16; o > 0; o >>= 1)
        mx = fmaxf(mx, __shfl_xor_sync(0xffffffffu, mx, o));
    float sum = 0.0f;
#pragma unroll
    for (int i = 0; i < 4; i++) {
        v[i].x = expf(v[i].x - mx); v[i].y = expf(v[i].y - mx);
        v[i].z = expf(v[i].z - mx); v[i].w = expf(v[i].w - mx);
        sum += v[i].x + v[i].y + v[i].z + v[i].w;
    }
#pragma unroll
    for (int o = 16; o > 0; o >>= 1)
        sum += __shfl_xor_sync(0xffffffffu, sum, o);
    float inv = 1.0f / sum;
#pragma unroll
    for (int i = 0; i < 4; i++) {
        v[i].x *= inv; v[i].y *= inv; v[i].z *= inv; v[i].w *= inv;
        *(float4*)(row + lane * 4 + i * 128) = v[i];
    }
}

// ---------------- O = P @ V  (per batch-head) ------------------------------
// grid: (SS/64, B*H), block 256
__global__ __launch_bounds__(256) void attn_av_kernel(
    const float* __restrict__ sc, const float* __restrict__ V,
    float* __restrict__ O)
{
    int qt = blockIdx.x * 64;
    int bh = blockIdx.y;
    int b  = bh / HH, h = bh % HH;
    __shared__ float Ps[64][68];    // [q][k] (padded)
    __shared__ float Vs[64][64];    // [k][d]
    int tid = threadIdx.x;
    int tx = tid & 15, ty = tid >> 4;
    float acc[4][4];
#pragma unroll
    for (int i = 0; i < 4; i++)
#pragma unroll
        for (int j = 0; j < 4; j++) acc[i][j] = 0.0f;

    for (int k0 = 0; k0 < SS; k0 += 64) {
#pragma unroll
        for (int i = 0; i < 4; i++) {
            int idx = tid + i * 256;
            int r   = idx >> 4;
            int c   = (idx & 15) << 2;
            *(float4*)&Ps[r][c] =
                *(const float4*)(sc + ((size_t)bh * SS + qt + r) * SS + k0 + c);
            *(float4*)&Vs[r][c] =
                *(const float4*)(V + (size_t)(b * SS + k0 + r) * D + h * DKH + c);
        }
        __syncthreads();
#pragma unroll
        for (int kk = 0; kk < 64; kk++) {
            float4 v4 = *(float4*)&Vs[kk][tx * 4];
            float vv[4] = {v4.x, v4.y, v4.z, v4.w};
#pragma unroll
            for (int i = 0; i < 4; i++) {
                float p = Ps[ty * 4 + i][kk];
#pragma unroll
                for (int j = 0; j < 4; j++)
                    acc[i][j] = fmaf(p, vv[j], acc[i][j]);
            }
        }
        __syncthreads();
    }
#pragma unroll
    for (int i = 0; i < 4; i++) {
        int q = qt + ty * 4 + i;
        float4 o = {acc[i][0], acc[i][1], acc[i][2], acc[i][3]};
        *(float4*)(O + (size_t)(b * SS + q) * D + h * DKH + tx * 4) = o;
    }
}

// ---------------- out = LayerNorm(x + a) * s + b ---------------------------
// grid = MROWS, block 256 (4 elems/thread)
__global__ void add_ln_kernel(const float* __restrict__ x,
                              const float* __restrict__ a,
                              const float* __restrict__ s,
                              const float* __restrict__ bb,
                              float* __restrict__ out)
{
    __shared__ float red[8];
    __shared__ float bc;
    int row = blockIdx.x, tid = threadIdx.x;
    int lane = tid & 31, wid = tid >> 5;
    const float* xr = x + (size_t)row * D;
    const float* ar = a + (size_t)row * D;
    float4 xv = *(const float4*)(xr + tid * 4);
    float4 av = *(const float4*)(ar + tid * 4);
    float v[4] = {xv.x + av.x, xv.y + av.y, xv.z + av.z, xv.w + av.w};

    float sum = v[0] + v[1] + v[2] + v[3];
#pragma unroll
    for (int o = 16; o > 0; o >>= 1) sum += __shfl_xor_sync(0xffffffffu, sum, o);
    if (lane == 0) red[wid] = sum;
    __syncthreads();
    if (tid == 0) {
        float t = 0.f;
#pragma unroll
        for (int i = 0; i < 8; i++) t += red[i];
        bc = t * (1.0f / D);
    }
    __syncthreads();
    float mean = bc;

    float d0 = v[0] - mean, d1 = v[1] - mean, d2 = v[2] - mean, d3 = v[3] - mean;
    float sq = d0 * d0 + d1 * d1 + d2 * d2 + d3 * d3;
#pragma unroll
    for (int o = 16; o > 0; o >>= 1) sq += __shfl_xor_sync(0xffffffffu, sq, o);
    __syncthreads();
    if (lane == 0) red[wid] = sq;
    __syncthreads();
    if (tid == 0) {
        float t = 0.f;
#pragma unroll
        for (int i = 0; i < 8; i++) t += red[i];
        bc = rsqrtf(t * (1.0f / D) + 1e-5f);
    }
    __syncthreads();
    float rstd = bc;

    float4 sv = *(const float4*)(s + tid * 4);
    float4 bv = *(const float4*)(bb + tid * 4);
    float4 o;
    o.x = d0 * rstd * sv.x + bv.x;
    o.y = d1 * rstd * sv.y + bv.y;
    o.z = d2 * rstd * sv.z + bv.z;
    o.w = d3 * rstd * sv.w + bv.w;
    *(float4*)(out + (size_t)row * D + tid * 4) = o;
}

// ---------------- host orchestration ---------------------------------------
static void run_mha(const float* xq, const float* xkv,
                    const float* w, const float* bias,
                    const int* toks, int causal,
                    float* pq, float* pk, float* pv, float* pao, float* psc,
                    float* out)
{
    dim3 gP(D / 128, MROWS / 128);   // (8,16)
    sgemm_tf32<<<gP, 256>>>(xq,  w + 0 * D * D, bias + 0 * D, nullptr, pq, MROWS, D, D, 0);
    sgemm_tf32<<<gP, 256>>>(xkv, w + 1 * D * D, bias + 1 * D, nullptr, pk, MROWS, D, D, 0);
    sgemm_tf32<<<gP, 256>>>(xkv, w + 2 * D * D, bias + 2 * D, nullptr, pv, MROWS, D, D, 0);
    attn_scores_kernel<<<dim3(SS / 64, SS / 64, BHN), 256>>>(pq, pk, toks, psc, causal);
    softmax_kernel<<<(BHN * SS) / 8, 256>>>(psc);
    attn_av_kernel<<<dim3(SS / 64, BHN), 256>>>(psc, pv, pao);
    sgemm_tf32<<<gP, 256>>>(pao, w + 3 * D * D, bias + 3 * D, nullptr, out, MROWS, D, D, 0);
}

extern "C" void kernel_launch(void* const* d_in, const int* in_sizes, int n_in,
                              void* d_out, int out_size)
{
    (void)in_sizes; (void)n_in; (void)out_size;
    const int*   src       = (const int*)  d_in[0];
    const int*   tgt       = (const int*)  d_in[1];
    const float* src_emb   = (const float*)d_in[2];
    const float* tgt_emb   = (const float*)d_in[3];
    const float* eaw       = (const float*)d_in[4];
    const float* eab       = (const float*)d_in[5];
    const float* ew1       = (const float*)d_in[6];
    const float* eb1       = (const float*)d_in[7];
    const float* ew2       = (const float*)d_in[8];
    const float* eb2       = (const float*)d_in[9];
    const float* els       = (const float*)d_in[10];
    const float* elb       = (const float*)d_in[11];
    const float* daw       = (const float*)d_in[12];
    const float* dab       = (const float*)d_in[13];
    const float* dw1       = (const float*)d_in[14];
    const float* db1       = (const float*)d_in[15];
    const float* dw2       = (const float*)d_in[16];
    const float* db2       = (const float*)d_in[17];
    const float* dls       = (const float*)d_in[18];
    const float* dlb       = (const float*)d_in[19];
    float* out = (float*)d_out;

    float *px, *py, *pq, *pk, *pv, *pao, *pt0, *ph, *psc;
    cudaGetSymbolAddress((void**)&px,  g_x);
    cudaGetSymbolAddress((void**)&py,  g_y);
    cudaGetSymbolAddress((void**)&pq,  g_q);
    cudaGetSymbolAddress((void**)&pk,  g_k);
    cudaGetSymbolAddress((void**)&pv,  g_v);
    cudaGetSymbolAddress((void**)&pao, g_ao);
    cudaGetSymbolAddress((void**)&pt0, g_t0);
    cudaGetSymbolAddress((void**)&ph,  g_h);
    cudaGetSymbolAddress((void**)&psc, g_sc);

    dim3 gP(D / 128, MROWS / 128);    // N=1024 GEMMs
    dim3 gF(FF / 128, MROWS / 128);   // N=4096 GEMMs

    // ----- encoder -----
    embed_kernel<<<MROWS, 256>>>(src, src_emb, px, SS);
    for (int i = 0; i < LL; i++) {
        run_mha(px, px, eaw + (size_t)i * 4 * D * D, eab + (size_t)i * 4 * D,
                src, 0, pq, pk, pv, pao, psc, pt0);
        add_ln_kernel<<<MROWS, 256>>>(px, pt0, els + (size_t)(i * 2 + 0) * D,
                                      elb + (size_t)(i * 2 + 0) * D, px);
        sgemm_tf32<<<gF, 256>>>(px, ew1 + (size_t)i * D * FF, eb1 + (size_t)i * FF,
                                nullptr, ph, MROWS, FF, D, FLAG_RELU);
        // f = h @ w2 + b2 + x   (double residual, as in reference)
        sgemm_tf32<<<gP, 256>>>(ph, ew2 + (size_t)i * FF * D, eb2 + (size_t)i * D,
                                px, pt0, MROWS, D, FF, FLAG_RES);
        add_ln_kernel<<<MROWS, 256>>>(px, pt0, els + (size_t)(i * 2 + 1) * D,
                                      elb + (size_t)(i * 2 + 1) * D, px);
    }

    // ----- decoder -----
    embed_kernel<<<MROWS, 256>>>(tgt, tgt_emb, py, SS);
    for (int i = 0; i < LL; i++) {
        // self-attention (causal + tgt pad mask)
        run_mha(py, py, daw + (size_t)(i * 2 + 0) * 4 * D * D,
                dab + (size_t)(i * 2 + 0) * 4 * D,
                tgt, 1, pq, pk, pv, pao, psc, pt0);
        add_ln_kernel<<<MROWS, 256>>>(py, pt0, dls + (size_t)(i * 3 + 0) * D,
                                      dlb + (size_t)(i * 3 + 0) * D, py);
        // cross-attention (keys/values from encoder output, src pad mask)
        run_mha(py, px, daw + (size_t)(i * 2 + 1) * 4 * D * D,
                dab + (size_t)(i * 2 + 1) * 4 * D,
                src, 0, pq, pk, pv, pao, psc, pt0);
        add_ln_kernel<<<MROWS, 256>>>(py, pt0, dls + (size_t)(i * 3 + 1) * D,
                                      dlb + (size_t)(i * 3 + 1) * D, py);
        // FFN (single residual via add_ln)
        sgemm_tf32<<<gF, 256>>>(py, dw1 + (size_t)i * D * FF, db1 + (size_t)i * FF,
                                nullptr, ph, MROWS, FF, D, FLAG_RELU);
        sgemm_tf32<<<gP, 256>>>(ph, dw2 + (size_t)i * FF * D, db2 + (size_t)i * D,
                                nullptr, pt0, MROWS, D, FF, 0);
        float* dst = (i == LL - 1) ? out : py;
        add_ln_kernel<<<MROWS, 256>>>(py, pt0, dls + (size_t)(i * 3 + 2) * D,
                                      dlb + (size_t)(i * 3 + 2) * D, dst);
    }
}

// round 5
// speedup vs baseline: 2.9425x; 1.2383x over previous
#include <cuda_runtime.h>
#include <math.h>
#include <stdint.h>

// ---------------- problem constants ----------------
#define D     1024
#define FF    4096
#define BB    4
#define SS    512          // S == T == 512
#define HH    16
#define DKH   64           // D / H
#define LL    4
#define MROWS (BB*SS)      // 2048
#define BHN   (BB*HH)      // 64

#define FLAG_RELU 1
#define FLAG_RES  2

// ---------------- scratch (device globals; no allocation allowed) ----------
__device__ float g_x [MROWS*D];
__device__ float g_y [MROWS*D];
__device__ float g_q [MROWS*D];
__device__ float g_k [MROWS*D];
__device__ float g_v [MROWS*D];
__device__ float g_ao[MROWS*D];
__device__ float g_t0[MROWS*D];
__device__ float g_h [MROWS*FF];
__device__ float g_sc[(size_t)BHN*SS*SS];

// ---------------- common PTX helpers ---------------------------------------
__device__ __forceinline__ uint32_t f2tf32(float f) {
    uint32_t u;
    asm("cvt.rna.tf32.f32 %0, %1;" : "=r"(u) : "f"(f));
    return u;
}

__device__ __forceinline__ void mma_tf32(float c[4], const uint32_t a[4],
                                         const uint32_t b[2]) {
    asm volatile(
        "mma.sync.aligned.m16n8k8.row.col.f32.tf32.tf32.f32 "
        "{%0,%1,%2,%3}, {%4,%5,%6,%7}, {%8,%9}, {%0,%1,%2,%3};"
        : "+f"(c[0]), "+f"(c[1]), "+f"(c[2]), "+f"(c[3])
        : "r"(a[0]), "r"(a[1]), "r"(a[2]), "r"(a[3]), "r"(b[0]), "r"(b[1]));
}

__device__ __forceinline__ void cp16(uint32_t dst, const void* src) {
    asm volatile("cp.async.cg.shared.global [%0], [%1], 16;"
                 :: "r"(dst), "l"(src));
}
#define CP_COMMIT() asm volatile("cp.async.commit_group;")
#define CP_WAIT0()  asm volatile("cp.async.wait_group 0;")

// ---------------- TF32 GEMM: cp.async 2-stage, consumer-side cvt ------------
// C = A[M,K] @ W[K,N] + bias (+relu / +res)
// 128x128 block tile, BK=16, 8 warps, warp tile 64x32 (4x4 m16n8k8 tiles).
__global__ __launch_bounds__(256) void sgemm_tf32(
    const float* __restrict__ A, const float* __restrict__ W,
    const float* __restrict__ bias, const float* __restrict__ res,
    float* __restrict__ C, int M, int N, int K, int flags)
{
    __shared__ float As[2][128][20];   // [m][k] fp32, stride 20 (16B-aligned, conflict-free)
    __shared__ float Bs[2][16][136];   // [k][n] fp32, stride 136 (16B-aligned, conflict-free)

    const int tid  = threadIdx.x;
    const int lane = tid & 31, wrp = tid >> 5;
    const int wm   = (wrp >> 2) * 64;
    const int wn   = (wrp & 3) * 32;
    const int l4   = lane >> 2, lq = lane & 3;
    const int bm   = blockIdx.y * 128, bn = blockIdx.x * 128;

    const int ar = tid >> 1,  ac = (tid & 1) * 8;
    const int br = tid >> 4,  bc = (tid & 15) * 8;

    const float* Aptr = A + (size_t)(bm + ar) * K + ac;
    const float* Wptr = W + (size_t)br * N + bn + bc;

    uint32_t sA0 = (uint32_t)__cvta_generic_to_shared(&As[0][ar][ac]);
    uint32_t sA1 = (uint32_t)__cvta_generic_to_shared(&As[1][ar][ac]);
    uint32_t sB0 = (uint32_t)__cvta_generic_to_shared(&Bs[0][br][bc]);
    uint32_t sB1 = (uint32_t)__cvta_generic_to_shared(&Bs[1][br][bc]);

    float acc[4][4][4];
#pragma unroll
    for (int i = 0; i < 4; i++)
#pragma unroll
        for (int j = 0; j < 4; j++)
#pragma unroll
            for (int r = 0; r < 4; r++) acc[i][j][r] = 0.0f;

    const int nt = K / 16;

    // preload tile 0 -> buffer 0
    cp16(sA0,      Aptr);
    cp16(sA0 + 16, Aptr + 4);
    cp16(sB0,      Wptr);
    cp16(sB0 + 16, Wptr + 4);
    CP_COMMIT();

    for (int t = 0; t < nt; t++) {
        CP_WAIT0();            // tile t resident
        __syncthreads();       // all warps past compute of t-1; see tile t

        if (t + 1 < nt) {      // overlap: tile t+1 flies during compute of t
            const float* Ap = Aptr + (size_t)(t + 1) * 16;
            const float* Wp = Wptr + (size_t)(t + 1) * 16 * N;
            uint32_t dA = ((t + 1) & 1) ? sA1 : sA0;
            uint32_t dB = ((t + 1) & 1) ? sB1 : sB0;
            cp16(dA,      Ap);
            cp16(dA + 16, Ap + 4);
            cp16(dB,      Wp);
            cp16(dB + 16, Wp + 4);
            CP_COMMIT();
        }

        const int buf = t & 1;
#pragma unroll
        for (int ks = 0; ks < 16; ks += 8) {
            uint32_t af[4][4], bf[4][2];
#pragma unroll
            for (int tm = 0; tm < 4; tm++) {
                const int m0 = wm + tm * 16 + l4;
                af[tm][0] = f2tf32(As[buf][m0][ks + lq]);
                af[tm][1] = f2tf32(As[buf][m0 + 8][ks + lq]);
                af[tm][2] = f2tf32(As[buf][m0][ks + lq + 4]);
                af[tm][3] = f2tf32(As[buf][m0 + 8][ks + lq + 4]);
            }
#pragma unroll
            for (int tn = 0; tn < 4; tn++) {
                const int n0 = wn + tn * 8 + l4;
                bf[tn][0] = f2tf32(Bs[buf][ks + lq][n0]);
                bf[tn][1] = f2tf32(Bs[buf][ks + lq + 4][n0]);
            }
#pragma unroll
            for (int tm = 0; tm < 4; tm++)
#pragma unroll
                for (int tn = 0; tn < 4; tn++)
                    mma_tf32(acc[tm][tn], af[tm], bf[tn]);
        }
    }

    // epilogue
#pragma unroll
    for (int tm = 0; tm < 4; tm++) {
        const int r0 = bm + wm + tm * 16 + l4;
        const int r1 = r0 + 8;
#pragma unroll
        for (int tn = 0; tn < 4; tn++) {
            const int col = bn + wn + tn * 8 + lq * 2;
            float2 v0 = {acc[tm][tn][0], acc[tm][tn][1]};
            float2 v1 = {acc[tm][tn][2], acc[tm][tn][3]};
            if (bias) {
                float2 bv = *(const float2*)(bias + col);
                v0.x += bv.x; v0.y += bv.y;
                v1.x += bv.x; v1.y += bv.y;
            }
            if (flags & FLAG_RELU) {
                v0.x = fmaxf(v0.x, 0.f); v0.y = fmaxf(v0.y, 0.f);
                v1.x = fmaxf(v1.x, 0.f); v1.y = fmaxf(v1.y, 0.f);
            }
            if (flags & FLAG_RES) {
                float2 q0 = *(const float2*)(res + (size_t)r0 * N + col);
                float2 q1 = *(const float2*)(res + (size_t)r1 * N + col);
                v0.x += q0.x; v0.y += q0.y;
                v1.x += q1.x; v1.y += q1.y;
            }
            *(float2*)(C + (size_t)r0 * N + col) = v0;
            *(float2*)(C + (size_t)r1 * N + col) = v1;
        }
    }
}

// ---------------- embedding + positional encoding -------------------------
__global__ void embed_kernel(const int* __restrict__ toks,
                             const float* __restrict__ emb,
                             float* __restrict__ out, int Sdim)
{
    int rs  = blockIdx.x;
    int pos = rs % Sdim;
    int tok = toks[rs];
    int j   = threadIdx.x * 4;
    float4 e = *(const float4*)(emb + (size_t)tok * D + j);
    float ev[4] = {e.x, e.y, e.z, e.w};
    float ov[4];
    const float c = 9.210340371976184f / (float)D;   // ln(10000)/D
#pragma unroll
    for (int q = 0; q < 4; q++) {
        int jj  = j + q;
        float div = expf(-(float)(jj & ~1) * c);
        float ang = (float)pos * div;
        float pe  = (jj & 1) ? cosf(ang) : sinf(ang);
        ov[q] = ev[q] + pe;
    }
    float4 o = {ov[0], ov[1], ov[2], ov[3]};
    *(float4*)(out + (size_t)rs * D + j) = o;
}

// ---------------- scores = QK^T * scale + mask (tf32 mma) -------------------
// grid: (SS/64, SS/64, B*H), block 128 (4 warps; warp w -> q rows w*16..)
__global__ __launch_bounds__(128) void attn_scores_mma(
    const float* __restrict__ Q, const float* __restrict__ Km,
    const int* __restrict__ toks, float* __restrict__ sc, int causal)
{
    const int kt = blockIdx.x * 64, qt = blockIdx.y * 64, bh = blockIdx.z;
    const int b = bh >> 4, h = bh & 15;
    __shared__ float Qs[64][68];   // [q][d]
    __shared__ float Ks[64][68];   // [k][d]
    const int tid = threadIdx.x;
    const int lane = tid & 31, w = tid >> 5;
    const int l4 = lane >> 2, lq = lane & 3;

#pragma unroll
    for (int i = 0; i < 8; i++) {
        int idx = tid + i * 128;
        int r = idx >> 4, c = (idx & 15) * 4;
        *(float4*)&Qs[r][c] =
            *(const float4*)(Q + (size_t)(b * SS + qt + r) * D + h * DKH + c);
        *(float4*)&Ks[r][c] =
            *(const float4*)(Km + (size_t)(b * SS + kt + r) * D + h * DKH + c);
    }
    __syncthreads();

    float acc[8][4];
#pragma unroll
    for (int i = 0; i < 8; i++)
#pragma unroll
        for (int j = 0; j < 4; j++) acc[i][j] = 0.0f;

    const int m0 = w * 16 + l4;
#pragma unroll
    for (int kk = 0; kk < DKH; kk += 8) {
        uint32_t a[4], bfr[8][2];
        a[0] = f2tf32(Qs[m0][kk + lq]);
        a[1] = f2tf32(Qs[m0 + 8][kk + lq]);
        a[2] = f2tf32(Qs[m0][kk + lq + 4]);
        a[3] = f2tf32(Qs[m0 + 8][kk + lq + 4]);
#pragma unroll
        for (int tn = 0; tn < 8; tn++) {
            bfr[tn][0] = f2tf32(Ks[tn * 8 + l4][kk + lq]);
            bfr[tn][1] = f2tf32(Ks[tn * 8 + l4][kk + lq + 4]);
        }
#pragma unroll
        for (int tn = 0; tn < 8; tn++)
            mma_tf32(acc[tn], a, bfr[tn]);
    }

    const float scale = 0.125f;              // 1/sqrt(64)
    const int q0 = qt + w * 16 + l4, q1 = q0 + 8;
#pragma unroll
    for (int tn = 0; tn < 8; tn++) {
        const int k0 = kt + tn * 8 + lq * 2;
        const bool p0 = toks[b * SS + k0] != 0;
        const bool p1 = toks[b * SS + k0 + 1] != 0;
        float2 r0, r1;
        r0.x = (p0 && (!causal || k0     <= q0)) ? acc[tn][0] * scale : -1e9f;
        r0.y = (p1 && (!causal || k0 + 1 <= q0)) ? acc[tn][1] * scale : -1e9f;
        r1.x = (p0 && (!causal || k0     <= q1)) ? acc[tn][2] * scale : -1e9f;
        r1.y = (p1 && (!causal || k0 + 1 <= q1)) ? acc[tn][3] * scale : -1e9f;
        *(float2*)(sc + ((size_t)bh * SS + q0) * SS + k0) = r0;
        *(float2*)(sc + ((size_t)bh * SS + q1) * SS + k0) = r1;
    }
}

// ---------------- row softmax (one warp per 512-wide row) ------------------
__global__ void softmax_kernel(float* __restrict__ sc)
{
    int gw   = (blockIdx.x * blockDim.x + threadIdx.x) >> 5;
    int lane = threadIdx.x & 31;
    float* row = sc + (size_t)gw * SS;
    float4 v[4];
    float mx = -1e30f;
#pragma unroll
    for (int i = 0; i < 4; i++) {
        v[i] = *(float4*)(row + lane * 4 + i * 128);
        mx = fmaxf(mx, fmaxf(fmaxf(v[i].x, v[i].y), fmaxf(v[i].z, v[i].w)));
    }
#pragma unroll
    for (int o = 16; o > 0; o >>= 1)
        mx = fmaxf(mx, __shfl_xor_sync(0xffffffffu, mx, o));
    float sum = 0.0f;
#pragma unroll
    for (int i = 0; i < 4; i++) {
        v[i].x = expf(v[i].x - mx); v[i].y = expf(v[i].y - mx);
        v[i].z = expf(v[i].z - mx); v[i].w = expf(v[i].w - mx);
        sum += v[i].x + v[i].y + v[i].z + v[i].w;
    }
#pragma unroll
    for (int o = 16; o > 0; o >>= 1)
        sum += __shfl_xor_sync(0xffffffffu, sum, o);
    float inv = 1.0f / sum;
#pragma unroll
    for (int i = 0; i < 4; i++) {
        v[i].x *= inv; v[i].y *= inv; v[i].z *= inv; v[i].w *= inv;
        *(float4*)(row + lane * 4 + i * 128) = v[i];
    }
}

// ---------------- O = P @ V  (tf32 mma, V transposed in smem) ---------------
// grid: (SS/64, B*H), block 128 (4 warps; warp w -> q rows w*16..)
__global__ __launch_bounds__(128) void attn_av_mma(
    const float* __restrict__ sc, const float* __restrict__ V,
    float* __restrict__ O)
{
    const int qt = blockIdx.x * 64, bh = blockIdx.y;
    const int b = bh >> 4, h = bh & 15;
    __shared__ float Ps[64][68];   // [q][k]
    __shared__ float Vs[64][68];   // [d][k]  (transposed)
    const int tid = threadIdx.x;
    const int lane = tid & 31, w = tid >> 5;
    const int l4 = lane >> 2, lq = lane & 3;

    float acc[8][4];
#pragma unroll
    for (int i = 0; i < 8; i++)
#pragma unroll
        for (int j = 0; j < 4; j++) acc[i][j] = 0.0f;

    const int m0 = w * 16 + l4;

    for (int k0 = 0; k0 < SS; k0 += 64) {
#pragma unroll
        for (int i = 0; i < 8; i++) {
            int idx = tid + i * 128;
            int r = idx >> 4, c = (idx & 15) * 4;
            *(float4*)&Ps[r][c] =
                *(const float4*)(sc + ((size_t)bh * SS + qt + r) * SS + k0 + c);
        }
        // V transpose: warp w owns d-cols [w*16, w*16+16); lane: 8 rows x 16B
        {
            const int dcol = w * 16 + (lane & 3) * 4;
#pragma unroll
            for (int g = 0; g < 8; g++) {
                const int r = g * 8 + (lane >> 2);
                float4 vv = *(const float4*)(V + (size_t)(b * SS + k0 + r) * D +
                                             h * DKH + dcol);
                Vs[dcol + 0][r] = vv.x;
                Vs[dcol + 1][r] = vv.y;
                Vs[dcol + 2][r] = vv.z;
                Vs[dcol + 3][r] = vv.w;
            }
        }
        __syncthreads();

#pragma unroll
        for (int kk = 0; kk < 64; kk += 8) {
            uint32_t a[4], bfr[8][2];
            a[0] = f2tf32(Ps[m0][kk + lq]);
            a[1] = f2tf32(Ps[m0 + 8][kk + lq]);
            a[2] = f2tf32(Ps[m0][kk + lq + 4]);
            a[3] = f2tf32(Ps[m0 + 8][kk + lq + 4]);
#pragma unroll
            for (int tn = 0; tn < 8; tn++) {
                bfr[tn][0] = f2tf32(Vs[tn * 8 + l4][kk + lq]);
                bfr[tn][1] = f2tf32(Vs[tn * 8 + l4][kk + lq + 4]);
            }
#pragma unroll
            for (int tn = 0; tn < 8; tn++)
                mma_tf32(acc[tn], a, bfr[tn]);
        }
        __syncthreads();
    }

    const int q0 = qt + w * 16 + l4, q1 = q0 + 8;
#pragma unroll
    for (int tn = 0; tn < 8; tn++) {
        const int col = h * DKH + tn * 8 + lq * 2;
        float2 o0 = {acc[tn][0], acc[tn][1]};
        float2 o1 = {acc[tn][2], acc[tn][3]};
        *(float2*)(O + (size_t)(b * SS + q0) * D + col) = o0;
        *(float2*)(O + (size_t)(b * SS + q1) * D + col) = o1;
    }
}

// ---------------- out = LayerNorm(x + a) * s + b ---------------------------
__global__ void add_ln_kernel(const float* __restrict__ x,
                              const float* __restrict__ a,
                              const float* __restrict__ s,
                              const float* __restrict__ bb,
                              float* __restrict__ out)
{
    __shared__ float red[8];
    __shared__ float bc;
    int row = blockIdx.x, tid = threadIdx.x;
    int lane = tid & 31, wid = tid >> 5;
    const float* xr = x + (size_t)row * D;
    const float* ar = a + (size_t)row * D;
    float4 xv = *(const float4*)(xr + tid * 4);
    float4 av = *(const float4*)(ar + tid * 4);
    float v[4] = {xv.x + av.x, xv.y + av.y, xv.z + av.z, xv.w + av.w};

    float sum = v[0] + v[1] + v[2] + v[3];
#pragma unroll
    for (int o = 16; o > 0; o >>= 1) sum += __shfl_xor_sync(0xffffffffu, sum, o);
    if (lane == 0) red[wid] = sum;
    __syncthreads();
    if (tid == 0) {
        float t = 0.f;
#pragma unroll
        for (int i = 0; i < 8; i++) t += red[i];
        bc = t * (1.0f / D);
    }
    __syncthreads();
    float mean = bc;

    float d0 = v[0] - mean, d1 = v[1] - mean, d2 = v[2] - mean, d3 = v[3] - mean;
    float sq = d0 * d0 + d1 * d1 + d2 * d2 + d3 * d3;
#pragma unroll
    for (int o = 16; o > 0; o >>= 1) sq += __shfl_xor_sync(0xffffffffu, sq, o);
    __syncthreads();
    if (lane == 0) red[wid] = sq;
    __syncthreads();
    if (tid == 0) {
        float t = 0.f;
#pragma unroll
        for (int i = 0; i < 8; i++) t += red[i];
        bc = rsqrtf(t * (1.0f / D) + 1e-5f);
    }
    __syncthreads();
    float rstd = bc;

    float4 sv = *(const float4*)(s + tid * 4);
    float4 bv = *(const float4*)(bb + tid * 4);
    float4 o;
    o.x = d0 * rstd * sv.x + bv.x;
    o.y = d1 * rstd * sv.y + bv.y;
    o.z = d2 * rstd * sv.z + bv.z;
    o.w = d3 * rstd * sv.w + bv.w;
    *(float4*)(out + (size_t)row * D + tid * 4) = o;
}

// ---------------- host orchestration ---------------------------------------
static void run_mha(const float* xq, const float* xkv,
                    const float* w, const float* bias,
                    const int* toks, int causal,
                    float* pq, float* pk, float* pv, float* pao, float* psc,
                    float* out)
{
    dim3 gP(D / 128, MROWS / 128);
    sgemm_tf32<<<gP, 256>>>(xq,  w + 0 * D * D, bias + 0 * D, nullptr, pq, MROWS, D, D, 0);
    sgemm_tf32<<<gP, 256>>>(xkv, w + 1 * D * D, bias + 1 * D, nullptr, pk, MROWS, D, D, 0);
    sgemm_tf32<<<gP, 256>>>(xkv, w + 2 * D * D, bias + 2 * D, nullptr, pv, MROWS, D, D, 0);
    attn_scores_mma<<<dim3(SS / 64, SS / 64, BHN), 128>>>(pq, pk, toks, psc, causal);
    softmax_kernel<<<(BHN * SS) / 8, 256>>>(psc);
    attn_av_mma<<<dim3(SS / 64, BHN), 128>>>(psc, pv, pao);
    sgemm_tf32<<<gP, 256>>>(pao, w + 3 * D * D, bias + 3 * D, nullptr, out, MROWS, D, D, 0);
}

extern "C" void kernel_launch(void* const* d_in, const int* in_sizes, int n_in,
                              void* d_out, int out_size)
{
    (void)in_sizes; (void)n_in; (void)out_size;
    const int*   src       = (const int*)  d_in[0];
    const int*   tgt       = (const int*)  d_in[1];
    const float* src_emb   = (const float*)d_in[2];
    const float* tgt_emb   = (const float*)d_in[3];
    const float* eaw       = (const float*)d_in[4];
    const float* eab       = (const float*)d_in[5];
    const float* ew1       = (const float*)d_in[6];
    const float* eb1       = (const float*)d_in[7];
    const float* ew2       = (const float*)d_in[8];
    const float* eb2       = (const float*)d_in[9];
    const float* els       = (const float*)d_in[10];
    const float* elb       = (const float*)d_in[11];
    const float* daw       = (const float*)d_in[12];
    const float* dab       = (const float*)d_in[13];
    const float* dw1       = (const float*)d_in[14];
    const float* db1       = (const float*)d_in[15];
    const float* dw2       = (const float*)d_in[16];
    const float* db2       = (const float*)d_in[17];
    const float* dls       = (const float*)d_in[18];
    const float* dlb       = (const float*)d_in[19];
    float* out = (float*)d_out;

    float *px, *py, *pq, *pk, *pv, *pao, *pt0, *ph, *psc;
    cudaGetSymbolAddress((void**)&px,  g_x);
    cudaGetSymbolAddress((void**)&py,  g_y);
    cudaGetSymbolAddress((void**)&pq,  g_q);
    cudaGetSymbolAddress((void**)&pk,  g_k);
    cudaGetSymbolAddress((void**)&pv,  g_v);
    cudaGetSymbolAddress((void**)&pao, g_ao);
    cudaGetSymbolAddress((void**)&pt0, g_t0);
    cudaGetSymbolAddress((void**)&ph,  g_h);
    cudaGetSymbolAddress((void**)&psc, g_sc);

    dim3 gP(D / 128, MROWS / 128);
    dim3 gF(FF / 128, MROWS / 128);

    // ----- encoder -----
    embed_kernel<<<MROWS, 256>>>(src, src_emb, px, SS);
    for (int i = 0; i < LL; i++) {
        run_mha(px, px, eaw + (size_t)i * 4 * D * D, eab + (size_t)i * 4 * D,
                src, 0, pq, pk, pv, pao, psc, pt0);
        add_ln_kernel<<<MROWS, 256>>>(px, pt0, els + (size_t)(i * 2 + 0) * D,
                                      elb + (size_t)(i * 2 + 0) * D, px);
        sgemm_tf32<<<gF, 256>>>(px, ew1 + (size_t)i * D * FF, eb1 + (size_t)i * FF,
                                nullptr, ph, MROWS, FF, D, FLAG_RELU);
        // f = h @ w2 + b2 + x   (double residual, as in reference)
        sgemm_tf32<<<gP, 256>>>(ph, ew2 + (size_t)i * FF * D, eb2 + (size_t)i * D,
                                px, pt0, MROWS, D, FF, FLAG_RES);
        add_ln_kernel<<<MROWS, 256>>>(px, pt0, els + (size_t)(i * 2 + 1) * D,
                                      elb + (size_t)(i * 2 + 1) * D, px);
    }

    // ----- decoder -----
    embed_kernel<<<MROWS, 256>>>(tgt, tgt_emb, py, SS);
    for (int i = 0; i < LL; i++) {
        run_mha(py, py, daw + (size_t)(i * 2 + 0) * 4 * D * D,
                dab + (size_t)(i * 2 + 0) * 4 * D,
                tgt, 1, pq, pk, pv, pao, psc, pt0);
        add_ln_kernel<<<MROWS, 256>>>(py, pt0, dls + (size_t)(i * 3 + 0) * D,
                                      dlb + (size_t)(i * 3 + 0) * D, py);
        run_mha(py, px, daw + (size_t)(i * 2 + 1) * 4 * D * D,
                dab + (size_t)(i * 2 + 1) * 4 * D,
                src, 0, pq, pk, pv, pao, psc, pt0);
        add_ln_kernel<<<MROWS, 256>>>(py, pt0, dls + (size_t)(i * 3 + 1) * D,
                                      dlb + (size_t)(i * 3 + 1) * D, py);
        sgemm_tf32<<<gF, 256>>>(py, dw1 + (size_t)i * D * FF, db1 + (size_t)i * FF,
                                nullptr, ph, MROWS, FF, D, FLAG_RELU);
        sgemm_tf32<<<gP, 256>>>(ph, dw2 + (size_t)i * FF * D, db2 + (size_t)i * D,
                                nullptr, pt0, MROWS, D, FF, 0);
        float* dst = (i == LL - 1) ? out : py;
        add_ln_kernel<<<MROWS, 256>>>(py, pt0, dls + (size_t)(i * 3 + 2) * D,
                                      dlb + (size_t)(i * 3 + 2) * D, dst);
    }
}